// round 1
// baseline (speedup 1.0000x reference)
#include <cuda_runtime.h>
#include <math.h>

// ---------------- problem constants ----------------
#define BB 1024
#define TT 128
#define FF 128
#define HH 512
#define G4 2048            // 4*HH
#define KC 768             // 2*FF + HH
#define BTn (BB*TT)        // 131072

constexpr size_t BTFc   = (size_t)BTn * FF;            // 16,777,216
constexpr size_t OFF_IMP = 0;
constexpr size_t OFF_CH1 = BTFc;
constexpr size_t OFF_HT  = 2 * BTFc;
constexpr size_t OFF_XH  = 2 * BTFc + (size_t)BB * HH;
constexpr size_t OFF_CH2 = OFF_XH + BTFc;
constexpr size_t OFF_ZH  = OFF_CH2 + BTFc;

// ---------------- device scratch (static, no allocs) ----------------
__device__ __align__(16) float g_gamma_x[(size_t)BTn * FF];   // 64 MB
__device__ __align__(16) float g_gamma_h[(size_t)BTn * HH];   // 256 MB
__device__ __align__(16) float g_alpha  [(size_t)BTn * FF];   // 64 MB
__device__ __align__(16) float g_h [BB * HH];
__device__ __align__(16) float g_c [BB * HH];
__device__ __align__(16) float g_xh[BB * FF];
__device__ __align__(16) float g_xc[BB * FF];
__device__ __align__(16) float g_cc[BB * FF];
__device__ __align__(16) float g_gates[BB * G4];
__device__ __align__(16) float g_Wod [FF * FF];
__device__ __align__(16) float g_Wcat[(size_t)G4 * KC];
__device__ __align__(16) float g_bcat[G4];

__device__ __forceinline__ float sigm(float x) { return 1.0f / (1.0f + expf(-x)); }

// ---------------- precompute: gamma_x, W_feat off-diag, W_cat, b_cat, zero state ----------------
__global__ void k_prep(const float* __restrict__ D,   const float* __restrict__ Wgx,
                       const float* __restrict__ bgx, const float* __restrict__ Wfeat,
                       const float* __restrict__ Wih, const float* __restrict__ Whh,
                       const float* __restrict__ bih, const float* __restrict__ bhh)
{
    size_t tid    = (size_t)blockIdx.x * blockDim.x + threadIdx.x;
    size_t stride = (size_t)gridDim.x * blockDim.x;

    for (size_t i = tid; i < (size_t)BTn * FF; i += stride) {
        int f = (int)(i & (FF - 1));
        float v = D[i] * Wgx[f * FF + f] + bgx[f];   // diagonal of W_gx only
        g_gamma_x[i] = expf(-fmaxf(v, 0.0f));
    }
    for (size_t i = tid; i < (size_t)G4 * KC; i += stride) {
        int n = (int)(i / KC), k = (int)(i % KC);
        g_Wcat[i] = (k < 2 * FF) ? Wih[(size_t)n * (2 * FF) + k]
                                 : Whh[(size_t)n * HH + (k - 2 * FF)];
    }
    for (size_t i = tid; i < (size_t)FF * FF; i += stride) {
        int r = (int)(i / FF), c2 = (int)(i % FF);
        g_Wod[i] = (r == c2) ? 0.0f : Wfeat[i];      // zero the diagonal
    }
    for (size_t i = tid; i < (size_t)G4; i += stride) g_bcat[i] = bih[i] + bhh[i];
    for (size_t i = tid; i < (size_t)BB * HH; i += stride) { g_h[i] = 0.0f; g_c[i] = 0.0f; }
}

// ---------------- fused tiled GEMM (64x64 tile, BK=16, 256 threads, 4x4/thread) ----------------
enum Mode { M_GH = 0, M_ALPHA = 1, M_XH = 2, M_ZH = 3, M_GATES = 4 };

template <int MODE>
__device__ __forceinline__ float4 loadA(int row, int k, int t,
    const float* __restrict__ X, const float* __restrict__ Mm, const float* __restrict__ D)
{
    if (MODE == M_GH) {
        return *(const float4*)(D + (size_t)row * FF + k);
    } else if (MODE == M_ALPHA) {
        if (k < FF) return *(const float4*)(g_gamma_x + (size_t)row * FF + k);
        return *(const float4*)(Mm + (size_t)row * FF + (k - FF));
    } else if (MODE == M_XH) {
        float4 h = *(const float4*)(g_h + (size_t)row * HH + k);
        float4 g = *(const float4*)(g_gamma_h + ((size_t)row * TT + t) * HH + k);
        return make_float4(h.x * g.x, h.y * g.y, h.z * g.z, h.w * g.w);
    } else if (MODE == M_ZH) {
        return *(const float4*)(g_xc + (size_t)row * FF + k);
    } else { // M_GATES : A row = [c_c(128) | m_t(128) | h*gamma_h(512)]
        if (k < FF)     return *(const float4*)(g_cc + (size_t)row * FF + k);
        if (k < 2 * FF) return *(const float4*)(Mm + ((size_t)row * TT + t) * FF + (k - FF));
        int kh = k - 2 * FF;
        float4 h = *(const float4*)(g_h + (size_t)row * HH + kh);
        float4 g = *(const float4*)(g_gamma_h + ((size_t)row * TT + t) * HH + kh);
        return make_float4(h.x * g.x, h.y * g.y, h.z * g.z, h.w * g.w);
    }
}

template <int MODE>
__global__ __launch_bounds__(256, 2) void k_gemm(int t,
    const float* __restrict__ X, const float* __restrict__ Mm,
    const float* __restrict__ D, const float* __restrict__ W,
    const float* __restrict__ bias, float* __restrict__ outp)
{
    constexpr int KD = (MODE == M_GH) ? FF : (MODE == M_ALPHA) ? 2 * FF
                     : (MODE == M_XH) ? HH : (MODE == M_ZH) ? FF : KC;

    __shared__ float As[16][68];
    __shared__ float Bs[16][68];

    const int tid = threadIdx.x;
    const int m0 = blockIdx.x * 64, n0 = blockIdx.y * 64;
    const int lr = tid >> 2;            // 0..63 : tile row for loading
    const int lk = (tid & 3) << 2;      // 0,4,8,12 : k quad for loading
    const int tx = tid & 15, ty = tid >> 4;

    const float* Wp = (MODE == M_ZH) ? g_Wod : (MODE == M_GATES) ? g_Wcat : W;

    float acc[4][4];
    #pragma unroll
    for (int i = 0; i < 4; i++)
        #pragma unroll
        for (int j = 0; j < 4; j++) acc[i][j] = 0.0f;

    for (int kt = 0; kt < KD; kt += 16) {
        float4 a = loadA<MODE>(m0 + lr, kt + lk, t, X, Mm, D);
        float4 b = *(const float4*)(Wp + (size_t)(n0 + lr) * KD + kt + lk);
        __syncthreads();   // previous compute done before smem overwrite
        As[lk + 0][lr] = a.x; As[lk + 1][lr] = a.y; As[lk + 2][lr] = a.z; As[lk + 3][lr] = a.w;
        Bs[lk + 0][lr] = b.x; Bs[lk + 1][lr] = b.y; Bs[lk + 2][lr] = b.z; Bs[lk + 3][lr] = b.w;
        __syncthreads();
        #pragma unroll
        for (int k = 0; k < 16; k++) {
            float4 av = *(const float4*)&As[k][ty << 2];
            float4 bv = *(const float4*)&Bs[k][tx << 2];
            float aa[4] = {av.x, av.y, av.z, av.w};
            float bb[4] = {bv.x, bv.y, bv.z, bv.w};
            #pragma unroll
            for (int i = 0; i < 4; i++)
                #pragma unroll
                for (int j = 0; j < 4; j++)
                    acc[i][j] = fmaf(aa[i], bb[j], acc[i][j]);
        }
    }

    // ---- fused epilogues ----
    #pragma unroll
    for (int i = 0; i < 4; i++) {
        const int r = m0 + (ty << 2) + i;
        #pragma unroll
        for (int j = 0; j < 4; j++) {
            const int c = n0 + (tx << 2) + j;
            float v = acc[i][j];
            if (MODE == M_GH) {
                v += bias[c];
                g_gamma_h[(size_t)r * HH + c] = expf(-fmaxf(v, 0.0f));
            } else if (MODE == M_ALPHA) {
                v += bias[c];
                g_alpha[(size_t)r * FF + c] = sigm(v);
            } else if (MODE == M_XH) {
                v += bias[c];
                size_t idx = ((size_t)r * TT + t) * FF + c;
                outp[OFF_XH + idx] = v;
                g_xh[r * FF + c] = v;
                float mm = Mm[idx], xx = X[idx];
                g_xc[r * FF + c] = mm * xx + (1.0f - mm) * v;
            } else if (MODE == M_ZH) {
                v += bias[c];
                size_t idx = ((size_t)r * TT + t) * FF + c;
                float al = g_alpha[idx];
                float xh = g_xh[r * FF + c];
                float ch = al * v + (1.0f - al) * xh;
                float mm = Mm[idx], xx = X[idx];
                float cc = mm * xx + (1.0f - mm) * ch;   // == imputed
                outp[OFF_ZH  + idx] = v;
                outp[OFF_CH1 + idx] = ch;
                outp[OFF_CH2 + idx] = ch;
                outp[OFF_IMP + idx] = cc;
                g_cc[r * FF + c] = cc;
            } else { // M_GATES
                g_gates[(size_t)r * G4 + c] = v + g_bcat[c];
            }
        }
    }
}

// ---------------- LSTM pointwise update ----------------
__global__ void k_lstm()
{
    int i = blockIdx.x * blockDim.x + threadIdx.x;
    if (i >= BB * HH) return;
    int b = i >> 9, j = i & (HH - 1);
    const float* gr = g_gates + (size_t)b * G4;
    float ig = sigm(gr[j]);
    float fg = sigm(gr[HH + j]);
    float gg = tanhf(gr[2 * HH + j]);
    float og = sigm(gr[3 * HH + j]);
    float c = fg * g_c[i] + ig * gg;
    g_c[i] = c;
    g_h[i] = og * tanhf(c);
}

__global__ void k_hT(float* __restrict__ outp)
{
    int i = blockIdx.x * blockDim.x + threadIdx.x;
    if (i < BB * HH) outp[OFF_HT + i] = g_h[i];
}

// ---------------- launch ----------------
extern "C" void kernel_launch(void* const* d_in, const int* in_sizes, int n_in,
                              void* d_out, int out_size)
{
    const float* X      = (const float*)d_in[0];
    const float* Mm     = (const float*)d_in[1];
    const float* D      = (const float*)d_in[2];
    const float* W_gh   = (const float*)d_in[3];
    const float* b_gh   = (const float*)d_in[4];
    const float* W_gx   = (const float*)d_in[5];
    const float* b_gx   = (const float*)d_in[6];
    const float* W_hist = (const float*)d_in[7];
    const float* b_hist = (const float*)d_in[8];
    const float* W_feat = (const float*)d_in[9];
    const float* b_feat = (const float*)d_in[10];
    const float* W_comb = (const float*)d_in[11];
    const float* b_comb = (const float*)d_in[12];
    const float* W_ih   = (const float*)d_in[13];
    const float* W_hh   = (const float*)d_in[14];
    const float* b_ih   = (const float*)d_in[15];
    const float* b_hh   = (const float*)d_in[16];
    float* outp = (float*)d_out;

    // Parallel precompute: everything that does not depend on the carry.
    k_prep<<<4096, 256>>>(D, W_gx, b_gx, W_feat, W_ih, W_hh, b_ih, b_hh);
    k_gemm<M_GH>   <<<dim3(BTn / 64, HH / 64), 256>>>(0, X, Mm, D, W_gh,   b_gh,   outp);
    k_gemm<M_ALPHA><<<dim3(BTn / 64, FF / 64), 256>>>(0, X, Mm, D, W_comb, b_comb, outp);

    // Serial scan: 4 launches per step.
    for (int t = 0; t < TT; t++) {
        k_gemm<M_XH>   <<<dim3(BB / 64, FF / 64), 256>>>(t, X, Mm, D, W_hist, b_hist, outp);
        k_gemm<M_ZH>   <<<dim3(BB / 64, FF / 64), 256>>>(t, X, Mm, D, nullptr, b_feat, outp);
        k_gemm<M_GATES><<<dim3(BB / 64, G4 / 64), 256>>>(t, X, Mm, D, nullptr, nullptr, outp);
        k_lstm<<<(BB * HH) / 256, 256>>>();
    }
    k_hT<<<(BB * HH) / 256, 256>>>(outp);
}